// round 5
// baseline (speedup 1.0000x reference)
#include <cuda_runtime.h>
#include <stdint.h>

// LightGCN: out = (x0 + x1 + x2 + x3 + x4) / 5,  x_{l+1} = A @ x_l  (COO SpMM)
// NUM_NODES=200000, EMB_DIM=64, NUM_EDGES=6400000, NUM_LAYERS=4
// NOTE: adj_rows/adj_cols are int32 on device (JAX default x64-disabled),
// despite the reference saying jnp.int64.

#define NUM_NODES 200000
#define EMB_DIM   64
#define NUM_EDGES 6400000
#define VEC4      (EMB_DIM / 4)          // 16 float4 per node row
#define NODE_F4   (NUM_NODES * VEC4)     // 3.2M float4 per buffer

// Scratch ping-pong buffers (allocation-free rule: static device arrays).
__device__ float4 g_bufA[NODE_F4];
__device__ float4 g_bufB[NODE_F4];

// ---------------------------------------------------------------------------
// out = 0.2 * embeds (d_out is poisoned; initialize fully), and zero bufA
// for the first scatter.
__global__ void k_init(const float4* __restrict__ emb,
                       float4* __restrict__ out,
                       float4* __restrict__ zero_dst)
{
    int i = blockIdx.x * blockDim.x + threadIdx.x;
    if (i < NODE_F4) {
        float4 v = emb[i];
        out[i] = make_float4(v.x * 0.2f, v.y * 0.2f, v.z * 0.2f, v.w * 0.2f);
        zero_dst[i] = make_float4(0.f, 0.f, 0.f, 0.f);
    }
}

// out += 0.2 * src, and zero the next layer's scatter destination (fused).
__global__ void k_axpy_zero(const float4* __restrict__ src,
                            float4* __restrict__ out,
                            float4* __restrict__ zero_dst)
{
    int i = blockIdx.x * blockDim.x + threadIdx.x;
    if (i < NODE_F4) {
        float4 s = src[i];
        float4 o = out[i];
        o.x += 0.2f * s.x; o.y += 0.2f * s.y;
        o.z += 0.2f * s.z; o.w += 0.2f * s.w;
        out[i] = o;
        zero_dst[i] = make_float4(0.f, 0.f, 0.f, 0.f);
    }
}

// out += 0.2 * src (last layer, nothing left to zero)
__global__ void k_axpy(const float4* __restrict__ src,
                       float4* __restrict__ out)
{
    int i = blockIdx.x * blockDim.x + threadIdx.x;
    if (i < NODE_F4) {
        float4 s = src[i];
        float4 o = out[i];
        o.x += 0.2f * s.x; o.y += 0.2f * s.y;
        o.z += 0.2f * s.z; o.w += 0.2f * s.w;
        out[i] = o;
    }
}

// ---------------------------------------------------------------------------
// Edge-parallel COO SpMM scatter: dst[row] += val * x[col]
// 16 threads per edge, each owning one float4 (4 dims) of the 64-dim row.
// Scatter uses red.global.add.v4.f32 (16B vector reduction, no return).
__global__ void k_spmm_scatter(const int*   __restrict__ rows,
                               const int*   __restrict__ cols,
                               const float* __restrict__ vals,
                               const float4* __restrict__ x,
                               float4*       __restrict__ dst)
{
    long long t = (long long)blockIdx.x * blockDim.x + threadIdx.x;
    int e = (int)(t >> 4);
    int q = (int)(t & 15);
    if (e >= NUM_EDGES) return;

    int   r = rows[e];
    int   c = cols[e];
    float v = vals[e];

    float4 xv = __ldg(&x[(long long)c * VEC4 + q]);
    float4 m  = make_float4(v * xv.x, v * xv.y, v * xv.z, v * xv.w);

    float4* p = &dst[(long long)r * VEC4 + q];
    asm volatile("red.global.add.v4.f32 [%0], {%1, %2, %3, %4};"
                 :: "l"(p), "f"(m.x), "f"(m.y), "f"(m.z), "f"(m.w)
                 : "memory");
}

// ---------------------------------------------------------------------------
extern "C" void kernel_launch(void* const* d_in, const int* in_sizes, int n_in,
                              void* d_out, int out_size)
{
    const float4* emb  = (const float4*)d_in[0];
    const int*    rows = (const int*)d_in[1];
    const int*    cols = (const int*)d_in[2];
    const float*  vals = (const float*)d_in[3];
    float4*       out  = (float4*)d_out;

    float4 *bufA, *bufB;
    cudaGetSymbolAddress((void**)&bufA, g_bufA);
    cudaGetSymbolAddress((void**)&bufB, g_bufB);

    const int TPB = 256;
    const int dense_blocks = (NODE_F4 + TPB - 1) / TPB;
    const long long spmm_threads = (long long)NUM_EDGES * 16;
    const int spmm_blocks = (int)((spmm_threads + TPB - 1) / TPB);

    // out = 0.2 * embeds; bufA = 0
    k_init<<<dense_blocks, TPB>>>(emb, out, bufA);

    const float4* src = (const float4*)emb;
    float4* dst = bufA;
    float4* other = bufB;

    for (int l = 0; l < 4; l++) {
        k_spmm_scatter<<<spmm_blocks, TPB>>>(rows, cols, vals, src, dst);
        if (l < 3) {
            // out += 0.2*dst, and zero the next destination buffer
            k_axpy_zero<<<dense_blocks, TPB>>>(dst, out, other);
        } else {
            k_axpy<<<dense_blocks, TPB>>>(dst, out);
        }
        // ping-pong
        src = dst;
        float4* tmp = other;
        other = dst;
        dst = tmp;
    }
}

// round 7
// speedup vs baseline: 2.3334x; 2.3334x over previous
#include <cuda_runtime.h>
#include <stdint.h>

// LightGCN: out = (x0+x1+x2+x3+x4)/5,  x_{l+1} = A @ x_l  (COO -> CSR SpMM)
// NUM_NODES=200000, EMB_DIM=64, NUM_EDGES=6400000, NUM_LAYERS=4
// adj_rows/adj_cols arrive as int32 (JAX x64 disabled).

#define NUM_NODES 200000
#define EMB_DIM   64
#define NUM_EDGES 6400000
#define VEC4      (EMB_DIM / 4)          // 16 float4 per node row
#define NODE_F4   (NUM_NODES * VEC4)     // 3.2M float4 per buffer

#define SCAN_B    1024
#define NPART     ((NUM_NODES + SCAN_B - 1) / SCAN_B)   // 196

// Scratch (allocation-free rule: static device arrays).
__device__ float4 g_bufA[NODE_F4];
__device__ float4 g_bufB[NODE_F4];
__device__ int    g_cnt[NUM_NODES];
__device__ int    g_rowptr[NUM_NODES + 1];
__device__ int    g_wpos[NUM_NODES];
__device__ int    g_part[256];
__device__ int2   g_edge[NUM_EDGES];     // {col, bitcast(val)} sorted by row

// ---------------------------------------------------------------------------
// out = 0.2*embeds (d_out poisoned -> init fully); zero histogram counters.
__global__ void k_init(const float4* __restrict__ emb, float4* __restrict__ out)
{
    int i = blockIdx.x * blockDim.x + threadIdx.x;
    if (i < NODE_F4) {
        float4 v = emb[i];
        out[i] = make_float4(v.x * 0.2f, v.y * 0.2f, v.z * 0.2f, v.w * 0.2f);
    }
    if (i < NUM_NODES) g_cnt[i] = 0;
}

// Histogram of destination rows.
__global__ void k_hist(const int* __restrict__ rows)
{
    int e = blockIdx.x * blockDim.x + threadIdx.x;
    if (e < NUM_EDGES) atomicAdd(&g_cnt[rows[e]], 1);
}

// Block-local exclusive scan of counts; per-block totals to g_part.
__global__ void k_scan_block()
{
    __shared__ int sh[SCAN_B];
    int t = threadIdx.x;
    int i = blockIdx.x * SCAN_B + t;
    int v = (i < NUM_NODES) ? g_cnt[i] : 0;
    sh[t] = v;
    __syncthreads();
    #pragma unroll
    for (int off = 1; off < SCAN_B; off <<= 1) {
        int tmp = 0;
        if (t >= off) tmp = sh[t - off];
        __syncthreads();
        if (t >= off) sh[t] += tmp;
        __syncthreads();
    }
    if (i < NUM_NODES) g_rowptr[i] = sh[t] - v;       // exclusive within block
    if (t == SCAN_B - 1) g_part[blockIdx.x] = sh[t];  // block total
}

// Exclusive scan of the (<=256) block totals. Single block.
__global__ void k_scan_part()
{
    __shared__ int sh[256];
    int t = threadIdx.x;
    int v = (t < NPART) ? g_part[t] : 0;
    sh[t] = v;
    __syncthreads();
    #pragma unroll
    for (int off = 1; off < 256; off <<= 1) {
        int tmp = 0;
        if (t >= off) tmp = sh[t - off];
        __syncthreads();
        if (t >= off) sh[t] += tmp;
        __syncthreads();
    }
    if (t < NPART) g_part[t] = sh[t] - v;             // exclusive
}

// Add block offsets; init write cursors; close rowptr.
__global__ void k_scan_add()
{
    int i = blockIdx.x * blockDim.x + threadIdx.x;
    if (i < NUM_NODES) {
        int r = g_rowptr[i] + g_part[i >> 10];
        g_rowptr[i] = r;
        g_wpos[i] = r;
    }
    if (i == 0) g_rowptr[NUM_NODES] = NUM_EDGES;
}

// Scatter edges into row-sorted (col,val) pairs.
__global__ void k_fill(const int* __restrict__ rows, const int* __restrict__ cols,
                       const float* __restrict__ vals)
{
    int e = blockIdx.x * blockDim.x + threadIdx.x;
    if (e < NUM_EDGES) {
        int r = rows[e];
        int p = atomicAdd(&g_wpos[r], 1);
        g_edge[p] = make_int2(cols[e], __float_as_int(vals[e]));
    }
}

// ---------------------------------------------------------------------------
// CSR SpMM, gather-only: dst[r] = sum v*x[c];  out[r] += 0.2*dst[r] (fused).
// 16 threads per row, each owns one float4 of the 64-dim embedding.
__global__ void k_spmm_csr(const float4* __restrict__ x,
                           float4* __restrict__ dst,
                           float4* __restrict__ out)
{
    int t = blockIdx.x * blockDim.x + threadIdx.x;
    int row = t >> 4;
    int q   = t & 15;
    if (row >= NUM_NODES) return;

    int e   = g_rowptr[row];
    int end = g_rowptr[row + 1];

    float4 acc = make_float4(0.f, 0.f, 0.f, 0.f);

    // Unroll by 2 for MLP in the dependent gather chain.
    for (; e + 1 < end; e += 2) {
        int2 cv0 = __ldg(&g_edge[e]);
        int2 cv1 = __ldg(&g_edge[e + 1]);
        float4 x0 = __ldg(&x[(long long)cv0.x * VEC4 + q]);
        float4 x1 = __ldg(&x[(long long)cv1.x * VEC4 + q]);
        float v0 = __int_as_float(cv0.y);
        float v1 = __int_as_float(cv1.y);
        acc.x += v0 * x0.x + v1 * x1.x;
        acc.y += v0 * x0.y + v1 * x1.y;
        acc.z += v0 * x0.z + v1 * x1.z;
        acc.w += v0 * x0.w + v1 * x1.w;
    }
    if (e < end) {
        int2 cv = __ldg(&g_edge[e]);
        float4 xv = __ldg(&x[(long long)cv.x * VEC4 + q]);
        float v = __int_as_float(cv.y);
        acc.x += v * xv.x; acc.y += v * xv.y;
        acc.z += v * xv.z; acc.w += v * xv.w;
    }

    long long o = (long long)row * VEC4 + q;
    dst[o] = acc;
    float4 ov = out[o];
    ov.x += 0.2f * acc.x; ov.y += 0.2f * acc.y;
    ov.z += 0.2f * acc.z; ov.w += 0.2f * acc.w;
    out[o] = ov;
}

// ---------------------------------------------------------------------------
extern "C" void kernel_launch(void* const* d_in, const int* in_sizes, int n_in,
                              void* d_out, int out_size)
{
    const float4* emb  = (const float4*)d_in[0];
    const int*    rows = (const int*)d_in[1];
    const int*    cols = (const int*)d_in[2];
    const float*  vals = (const float*)d_in[3];
    float4*       out  = (float4*)d_out;

    float4 *bufA, *bufB;
    cudaGetSymbolAddress((void**)&bufA, g_bufA);
    cudaGetSymbolAddress((void**)&bufB, g_bufB);

    const int TPB = 256;
    const int dense_blocks = (NODE_F4 + TPB - 1) / TPB;       // covers NUM_NODES too
    const int edge_blocks  = (NUM_EDGES + TPB - 1) / TPB;
    const int node_blocks  = (NUM_NODES + TPB - 1) / TPB;

    // CSR build (runs inside the captured graph every call)
    k_init<<<dense_blocks, TPB>>>(emb, out);
    k_hist<<<edge_blocks, TPB>>>(rows);
    k_scan_block<<<NPART, SCAN_B>>>();
    k_scan_part<<<1, 256>>>();
    k_scan_add<<<node_blocks, TPB>>>();
    k_fill<<<edge_blocks, TPB>>>(rows, cols, vals);

    // 4 propagation layers, gather-only, axpy fused.
    const float4* src = emb;
    float4* dst = bufA;
    float4* other = bufB;
    for (int l = 0; l < 4; l++) {
        k_spmm_csr<<<dense_blocks, TPB>>>(src, dst, out);
        src = dst;
        float4* tmp = other;
        other = dst;
        dst = tmp;
    }
}

// round 9
// speedup vs baseline: 3.2004x; 1.3716x over previous
#include <cuda_runtime.h>
#include <cuda_fp16.h>
#include <stdint.h>

// LightGCN: out = (x0+x1+x2+x3+x4)/5,  x_{l+1} = A @ x_l  (COO -> CSR SpMM)
// NUM_NODES=200000, EMB_DIM=64, NUM_EDGES=6400000, NUM_LAYERS=4
// adj_rows/adj_cols arrive as int32 (JAX x64 disabled).
// Intermediate x_l buffers stored fp16 (halves the dominant gather stream);
// all accumulation is fp32, out stays fp32.

#define NUM_NODES 200000
#define EMB_DIM   64
#define NUM_EDGES 6400000
#define VEC4      (EMB_DIM / 4)           // 16 float4 per node row (fp32 out)
#define NODE_F4   (NUM_NODES * VEC4)
#define ROW_U4    (EMB_DIM / 8)           // 8 uint4 per node row (fp16 x)
#define NODE_U4   (NUM_NODES * ROW_U4)

#define SCAN_B    1024
#define NPART     ((NUM_NODES + SCAN_B - 1) / SCAN_B)   // 196

// Scratch (allocation-free rule: static device arrays).
__device__ uint4  g_bufA[NODE_U4];        // fp16 x buffers (25.6 MB each)
__device__ uint4  g_bufB[NODE_U4];
__device__ uint4  g_embH[NODE_U4];        // fp16 copy of embeds
__device__ int    g_cnt[NUM_NODES];
__device__ int    g_rowptr[NUM_NODES + 1];
__device__ int    g_wpos[NUM_NODES];
__device__ int    g_part[256];
__device__ int2   g_edge[NUM_EDGES];      // {col, bitcast(val)} sorted by row

// ---------------------------------------------------------------------------
// out = 0.2*embeds (fp32, d_out poisoned -> init fully), embH = fp16(embeds),
// zero histogram counters. i indexes float4 (4 dims).
__global__ void k_init(const float4* __restrict__ emb, float4* __restrict__ out)
{
    int i = blockIdx.x * blockDim.x + threadIdx.x;
    if (i < NODE_F4) {
        float4 v = emb[i];
        out[i] = make_float4(v.x * 0.2f, v.y * 0.2f, v.z * 0.2f, v.w * 0.2f);
        // fp16 copy: float4 -> 2x half2 = 8 bytes
        __half2 h0 = __floats2half2_rn(v.x, v.y);
        __half2 h1 = __floats2half2_rn(v.z, v.w);
        uint2* dst8 = reinterpret_cast<uint2*>(g_embH);
        dst8[i] = make_uint2(*(unsigned*)&h0, *(unsigned*)&h1);
    }
    if (i < NUM_NODES) g_cnt[i] = 0;
}

// Histogram of destination rows.
__global__ void k_hist(const int* __restrict__ rows)
{
    int e = blockIdx.x * blockDim.x + threadIdx.x;
    if (e < NUM_EDGES) atomicAdd(&g_cnt[rows[e]], 1);
}

// Block-local exclusive scan of counts; per-block totals to g_part.
__global__ void k_scan_block()
{
    __shared__ int sh[SCAN_B];
    int t = threadIdx.x;
    int i = blockIdx.x * SCAN_B + t;
    int v = (i < NUM_NODES) ? g_cnt[i] : 0;
    sh[t] = v;
    __syncthreads();
    #pragma unroll
    for (int off = 1; off < SCAN_B; off <<= 1) {
        int tmp = 0;
        if (t >= off) tmp = sh[t - off];
        __syncthreads();
        if (t >= off) sh[t] += tmp;
        __syncthreads();
    }
    if (i < NUM_NODES) g_rowptr[i] = sh[t] - v;
    if (t == SCAN_B - 1) g_part[blockIdx.x] = sh[t];
}

// Exclusive scan of block totals. Single block.
__global__ void k_scan_part()
{
    __shared__ int sh[256];
    int t = threadIdx.x;
    int v = (t < NPART) ? g_part[t] : 0;
    sh[t] = v;
    __syncthreads();
    #pragma unroll
    for (int off = 1; off < 256; off <<= 1) {
        int tmp = 0;
        if (t >= off) tmp = sh[t - off];
        __syncthreads();
        if (t >= off) sh[t] += tmp;
        __syncthreads();
    }
    if (t < NPART) g_part[t] = sh[t] - v;
}

// Add block offsets; init write cursors; close rowptr.
__global__ void k_scan_add()
{
    int i = blockIdx.x * blockDim.x + threadIdx.x;
    if (i < NUM_NODES) {
        int r = g_rowptr[i] + g_part[i >> 10];
        g_rowptr[i] = r;
        g_wpos[i] = r;
    }
    if (i == 0) g_rowptr[NUM_NODES] = NUM_EDGES;
}

// Scatter edges into row-sorted (col,val) pairs.
__global__ void k_fill(const int* __restrict__ rows, const int* __restrict__ cols,
                       const float* __restrict__ vals)
{
    int e = blockIdx.x * blockDim.x + threadIdx.x;
    if (e < NUM_EDGES) {
        int r = rows[e];
        int p = atomicAdd(&g_wpos[r], 1);
        g_edge[p] = make_int2(cols[e], __float_as_int(vals[e]));
    }
}

// ---------------------------------------------------------------------------
// 8 fp32 accumulators += v * fp16x8(u)
__device__ __forceinline__ void fma8(float acc[8], uint4 u, float v)
{
    __half2 h0 = *reinterpret_cast<__half2*>(&u.x);
    __half2 h1 = *reinterpret_cast<__half2*>(&u.y);
    __half2 h2 = *reinterpret_cast<__half2*>(&u.z);
    __half2 h3 = *reinterpret_cast<__half2*>(&u.w);
    float2 f0 = __half22float2(h0);
    float2 f1 = __half22float2(h1);
    float2 f2 = __half22float2(h2);
    float2 f3 = __half22float2(h3);
    acc[0] = fmaf(v, f0.x, acc[0]); acc[1] = fmaf(v, f0.y, acc[1]);
    acc[2] = fmaf(v, f1.x, acc[2]); acc[3] = fmaf(v, f1.y, acc[3]);
    acc[4] = fmaf(v, f2.x, acc[4]); acc[5] = fmaf(v, f2.y, acc[5]);
    acc[6] = fmaf(v, f3.x, acc[6]); acc[7] = fmaf(v, f3.y, acc[7]);
}

// CSR SpMM, gather-only, fp16 x: dst[r] = fp16(sum v*x[c]);
// out[r] += 0.2*sum (fp32, pre-rounding). 8 threads per row, 8 dims each.
__global__ void k_spmm_csr(const uint4* __restrict__ x,
                           uint4* __restrict__ dst,
                           float4* __restrict__ out)
{
    int t = blockIdx.x * blockDim.x + threadIdx.x;
    int row = t >> 3;
    int q   = t & 7;
    if (row >= NUM_NODES) return;

    int e   = g_rowptr[row];
    int end = g_rowptr[row + 1];

    float acc[8] = {0.f, 0.f, 0.f, 0.f, 0.f, 0.f, 0.f, 0.f};

    // Unroll by 2 for MLP in the dependent gather chain.
    for (; e + 1 < end; e += 2) {
        int2 cv0 = __ldg(&g_edge[e]);
        int2 cv1 = __ldg(&g_edge[e + 1]);
        uint4 x0 = __ldg(&x[cv0.x * ROW_U4 + q]);
        uint4 x1 = __ldg(&x[cv1.x * ROW_U4 + q]);
        fma8(acc, x0, __int_as_float(cv0.y));
        fma8(acc, x1, __int_as_float(cv1.y));
    }
    if (e < end) {
        int2 cv = __ldg(&g_edge[e]);
        uint4 xv = __ldg(&x[cv.x * ROW_U4 + q]);
        fma8(acc, xv, __int_as_float(cv.y));
    }

    // fp16 store of x_{l+1}
    __half2 h0 = __floats2half2_rn(acc[0], acc[1]);
    __half2 h1 = __floats2half2_rn(acc[2], acc[3]);
    __half2 h2 = __floats2half2_rn(acc[4], acc[5]);
    __half2 h3 = __floats2half2_rn(acc[6], acc[7]);
    dst[row * ROW_U4 + q] = make_uint4(*(unsigned*)&h0, *(unsigned*)&h1,
                                       *(unsigned*)&h2, *(unsigned*)&h3);

    // fp32 out += 0.2*acc  (2 float4 per lane)
    long long o = (long long)row * VEC4 + q * 2;
    float4 a = out[o];
    float4 b = out[o + 1];
    a.x += 0.2f * acc[0]; a.y += 0.2f * acc[1];
    a.z += 0.2f * acc[2]; a.w += 0.2f * acc[3];
    b.x += 0.2f * acc[4]; b.y += 0.2f * acc[5];
    b.z += 0.2f * acc[6]; b.w += 0.2f * acc[7];
    out[o]     = a;
    out[o + 1] = b;
}

// ---------------------------------------------------------------------------
extern "C" void kernel_launch(void* const* d_in, const int* in_sizes, int n_in,
                              void* d_out, int out_size)
{
    const float4* emb  = (const float4*)d_in[0];
    const int*    rows = (const int*)d_in[1];
    const int*    cols = (const int*)d_in[2];
    const float*  vals = (const float*)d_in[3];
    float4*       out  = (float4*)d_out;

    uint4 *bufA, *bufB, *embH;
    cudaGetSymbolAddress((void**)&bufA, g_bufA);
    cudaGetSymbolAddress((void**)&bufB, g_bufB);
    cudaGetSymbolAddress((void**)&embH, g_embH);

    const int TPB = 256;
    const int dense_blocks = (NODE_F4 + TPB - 1) / TPB;
    const int edge_blocks  = (NUM_EDGES + TPB - 1) / TPB;
    const int node_blocks  = (NUM_NODES + TPB - 1) / TPB;
    const long long spmm_threads = (long long)NUM_NODES * 8;
    const int spmm_blocks = (int)((spmm_threads + TPB - 1) / TPB);

    // CSR build + init (inside captured graph, every call)
    k_init<<<dense_blocks, TPB>>>(emb, out);
    k_hist<<<edge_blocks, TPB>>>(rows);
    k_scan_block<<<NPART, SCAN_B>>>();
    k_scan_part<<<1, 256>>>();
    k_scan_add<<<node_blocks, TPB>>>();
    k_fill<<<edge_blocks, TPB>>>(rows, cols, vals);

    // 4 propagation layers, gather-only, fp16 x, fp32 out fused.
    const uint4* src = embH;
    uint4* dst = bufA;
    uint4* other = bufB;
    for (int l = 0; l < 4; l++) {
        k_spmm_csr<<<spmm_blocks, TPB>>>(src, dst, out);
        src = dst;
        uint4* tmp = other;
        other = dst;
        dst = tmp;
    }
}

// round 11
// speedup vs baseline: 3.4453x; 1.0765x over previous
#include <cuda_runtime.h>
#include <cuda_fp16.h>
#include <stdint.h>

// LightGCN: out = (x0+x1+x2+x3+x4)/5,  x_{l+1} = A @ x_l  (COO -> CSR SpMM)
// NUM_NODES=200000, EMB_DIM=64, NUM_EDGES=6400000, NUM_LAYERS=4
// adj_rows/adj_cols arrive as int32 (JAX x64 disabled).
// x_l stored fp16 (halves dominant gather stream); fp32 accumulation.
// Mean-combine deferred to one final dense pass over 4 layer buffers.

#define NUM_NODES 200000
#define EMB_DIM   64
#define NUM_EDGES 6400000
#define VEC4      (EMB_DIM / 4)           // 16 float4 per node row (fp32)
#define NODE_F4   (NUM_NODES * VEC4)
#define ROW_U4    (EMB_DIM / 8)           // 8 uint4 per node row (fp16)
#define NODE_U4   (NUM_NODES * ROW_U4)

#define SCAN_B    1024
#define NPART     ((NUM_NODES + SCAN_B - 1) / SCAN_B)   // 196

// Scratch (allocation-free rule: static device arrays).
__device__ uint4  g_embH[NODE_U4];        // fp16 embeds
__device__ uint4  g_x1[NODE_U4];          // fp16 layer outputs
__device__ uint4  g_x2[NODE_U4];
__device__ uint4  g_x3[NODE_U4];
__device__ uint4  g_x4[NODE_U4];
__device__ int    g_cnt[NUM_NODES];
__device__ int    g_rowptr[NUM_NODES + 1];
__device__ int    g_wpos[NUM_NODES];
__device__ int    g_part[256];
__device__ int2   g_edge[NUM_EDGES];      // {col, bitcast(val)} sorted by row

// ---------------------------------------------------------------------------
__global__ void k_zero_cnt()
{
    int i = blockIdx.x * blockDim.x + threadIdx.x;
    if (i < NUM_NODES) g_cnt[i] = 0;
}

// Fused: row histogram (6.4M edges) + fp16 copy of embeds (3.2M float4).
__global__ void k_init_hist(const int* __restrict__ rows,
                            const float4* __restrict__ emb)
{
    int i = blockIdx.x * blockDim.x + threadIdx.x;
    if (i < NUM_EDGES) atomicAdd(&g_cnt[rows[i]], 1);
    if (i < NODE_F4) {
        float4 v = emb[i];
        __half2 h0 = __floats2half2_rn(v.x, v.y);
        __half2 h1 = __floats2half2_rn(v.z, v.w);
        reinterpret_cast<uint2*>(g_embH)[i] =
            make_uint2(*(unsigned*)&h0, *(unsigned*)&h1);
    }
}

// Block-local exclusive scan of counts; per-block totals to g_part.
__global__ void k_scan_block()
{
    __shared__ int sh[SCAN_B];
    int t = threadIdx.x;
    int i = blockIdx.x * SCAN_B + t;
    int v = (i < NUM_NODES) ? g_cnt[i] : 0;
    sh[t] = v;
    __syncthreads();
    #pragma unroll
    for (int off = 1; off < SCAN_B; off <<= 1) {
        int tmp = 0;
        if (t >= off) tmp = sh[t - off];
        __syncthreads();
        if (t >= off) sh[t] += tmp;
        __syncthreads();
    }
    if (i < NUM_NODES) g_rowptr[i] = sh[t] - v;
    if (t == SCAN_B - 1) g_part[blockIdx.x] = sh[t];
}

// Exclusive scan of block totals. Single block.
__global__ void k_scan_part()
{
    __shared__ int sh[256];
    int t = threadIdx.x;
    int v = (t < NPART) ? g_part[t] : 0;
    sh[t] = v;
    __syncthreads();
    #pragma unroll
    for (int off = 1; off < 256; off <<= 1) {
        int tmp = 0;
        if (t >= off) tmp = sh[t - off];
        __syncthreads();
        if (t >= off) sh[t] += tmp;
        __syncthreads();
    }
    if (t < NPART) g_part[t] = sh[t] - v;
}

// Add block offsets; init write cursors; close rowptr.
__global__ void k_scan_add()
{
    int i = blockIdx.x * blockDim.x + threadIdx.x;
    if (i < NUM_NODES) {
        int r = g_rowptr[i] + g_part[i >> 10];
        g_rowptr[i] = r;
        g_wpos[i] = r;
    }
    if (i == 0) g_rowptr[NUM_NODES] = NUM_EDGES;
}

// Scatter edges into row-sorted (col,val) pairs.
__global__ void k_fill(const int* __restrict__ rows, const int* __restrict__ cols,
                       const float* __restrict__ vals)
{
    int e = blockIdx.x * blockDim.x + threadIdx.x;
    if (e < NUM_EDGES) {
        int r = rows[e];
        int p = atomicAdd(&g_wpos[r], 1);
        g_edge[p] = make_int2(cols[e], __float_as_int(vals[e]));
    }
}

// ---------------------------------------------------------------------------
// 8 fp32 accumulators += v * fp16x8(u)
__device__ __forceinline__ void fma8(float acc[8], uint4 u, float v)
{
    float2 f0 = __half22float2(*reinterpret_cast<__half2*>(&u.x));
    float2 f1 = __half22float2(*reinterpret_cast<__half2*>(&u.y));
    float2 f2 = __half22float2(*reinterpret_cast<__half2*>(&u.z));
    float2 f3 = __half22float2(*reinterpret_cast<__half2*>(&u.w));
    acc[0] = fmaf(v, f0.x, acc[0]); acc[1] = fmaf(v, f0.y, acc[1]);
    acc[2] = fmaf(v, f1.x, acc[2]); acc[3] = fmaf(v, f1.y, acc[3]);
    acc[4] = fmaf(v, f2.x, acc[4]); acc[5] = fmaf(v, f2.y, acc[5]);
    acc[6] = fmaf(v, f3.x, acc[6]); acc[7] = fmaf(v, f3.y, acc[7]);
}

// CSR SpMM, gather-only, fp16 x -> fp16 dst. 8 threads/row, 8 dims each.
__global__ void k_spmm_csr(const uint4* __restrict__ x,
                           uint4* __restrict__ dst)
{
    int t = blockIdx.x * blockDim.x + threadIdx.x;
    int row = t >> 3;
    int q   = t & 7;
    if (row >= NUM_NODES) return;

    int e   = g_rowptr[row];
    int end = g_rowptr[row + 1];

    float acc[8] = {0.f, 0.f, 0.f, 0.f, 0.f, 0.f, 0.f, 0.f};

    // Unroll by 4 for MLP in the gather chain.
    for (; e + 3 < end; e += 4) {
        int2 cv0 = __ldg(&g_edge[e]);
        int2 cv1 = __ldg(&g_edge[e + 1]);
        int2 cv2 = __ldg(&g_edge[e + 2]);
        int2 cv3 = __ldg(&g_edge[e + 3]);
        uint4 x0 = __ldg(&x[cv0.x * ROW_U4 + q]);
        uint4 x1 = __ldg(&x[cv1.x * ROW_U4 + q]);
        uint4 x2 = __ldg(&x[cv2.x * ROW_U4 + q]);
        uint4 x3 = __ldg(&x[cv3.x * ROW_U4 + q]);
        fma8(acc, x0, __int_as_float(cv0.y));
        fma8(acc, x1, __int_as_float(cv1.y));
        fma8(acc, x2, __int_as_float(cv2.y));
        fma8(acc, x3, __int_as_float(cv3.y));
    }
    for (; e < end; e++) {
        int2 cv = __ldg(&g_edge[e]);
        uint4 xv = __ldg(&x[cv.x * ROW_U4 + q]);
        fma8(acc, xv, __int_as_float(cv.y));
    }

    __half2 h0 = __floats2half2_rn(acc[0], acc[1]);
    __half2 h1 = __floats2half2_rn(acc[2], acc[3]);
    __half2 h2 = __floats2half2_rn(acc[4], acc[5]);
    __half2 h3 = __floats2half2_rn(acc[6], acc[7]);
    dst[row * ROW_U4 + q] = make_uint4(*(unsigned*)&h0, *(unsigned*)&h1,
                                       *(unsigned*)&h2, *(unsigned*)&h3);
}

// ---------------------------------------------------------------------------
// out = 0.2 * (emb + x1 + x2 + x3 + x4); one dense pass, 4 dims per thread.
__global__ void k_final(const float4* __restrict__ emb, float4* __restrict__ out)
{
    int i = blockIdx.x * blockDim.x + threadIdx.x;
    if (i >= NODE_F4) return;

    float4 s = emb[i];
    const uint2* b1 = reinterpret_cast<const uint2*>(g_x1);
    const uint2* b2 = reinterpret_cast<const uint2*>(g_x2);
    const uint2* b3 = reinterpret_cast<const uint2*>(g_x3);
    const uint2* b4 = reinterpret_cast<const uint2*>(g_x4);

    uint2 u1 = b1[i], u2 = b2[i], u3 = b3[i], u4 = b4[i];
    #define ADD8(u) { \
        float2 p = __half22float2(*reinterpret_cast<__half2*>(&(u).x)); \
        float2 r = __half22float2(*reinterpret_cast<__half2*>(&(u).y)); \
        s.x += p.x; s.y += p.y; s.z += r.x; s.w += r.y; }
    ADD8(u1); ADD8(u2); ADD8(u3); ADD8(u4);
    #undef ADD8

    out[i] = make_float4(s.x * 0.2f, s.y * 0.2f, s.z * 0.2f, s.w * 0.2f);
}

// ---------------------------------------------------------------------------
extern "C" void kernel_launch(void* const* d_in, const int* in_sizes, int n_in,
                              void* d_out, int out_size)
{
    const float4* emb  = (const float4*)d_in[0];
    const int*    rows = (const int*)d_in[1];
    const int*    cols = (const int*)d_in[2];
    const float*  vals = (const float*)d_in[3];
    float4*       out  = (float4*)d_out;

    uint4 *embH, *x1, *x2, *x3, *x4;
    cudaGetSymbolAddress((void**)&embH, g_embH);
    cudaGetSymbolAddress((void**)&x1, g_x1);
    cudaGetSymbolAddress((void**)&x2, g_x2);
    cudaGetSymbolAddress((void**)&x3, g_x3);
    cudaGetSymbolAddress((void**)&x4, g_x4);

    const int TPB = 256;
    const int dense_blocks = (NODE_F4 + TPB - 1) / TPB;
    const int edge_blocks  = (NUM_EDGES + TPB - 1) / TPB;
    const int node_blocks  = (NUM_NODES + TPB - 1) / TPB;
    const long long spmm_threads = (long long)NUM_NODES * 8;
    const int spmm_blocks = (int)((spmm_threads + TPB - 1) / TPB);

    // CSR build (inside captured graph, every call)
    k_zero_cnt<<<node_blocks, TPB>>>();
    k_init_hist<<<edge_blocks, TPB>>>(rows, emb);
    k_scan_block<<<NPART, SCAN_B>>>();
    k_scan_part<<<1, 256>>>();
    k_scan_add<<<node_blocks, TPB>>>();
    k_fill<<<edge_blocks, TPB>>>(rows, cols, vals);

    // 4 propagation layers, gather-only.
    k_spmm_csr<<<spmm_blocks, TPB>>>(embH, x1);
    k_spmm_csr<<<spmm_blocks, TPB>>>(x1, x2);
    k_spmm_csr<<<spmm_blocks, TPB>>>(x2, x3);
    k_spmm_csr<<<spmm_blocks, TPB>>>(x3, x4);

    // out = mean of {emb, x1..x4}
    k_final<<<dense_blocks, TPB>>>(emb, out);
}

// round 14
// speedup vs baseline: 3.6076x; 1.0471x over previous
#include <cuda_runtime.h>
#include <cuda_fp16.h>
#include <stdint.h>

// LightGCN: out = (x0+x1+x2+x3+x4)/5,  x_{l+1} = A @ x_l  (COO -> CSR SpMM)
// NUM_NODES=200000, EMB_DIM=64, NUM_EDGES=6400000, NUM_LAYERS=4
// adj_rows/adj_cols arrive as int32 (JAX x64 disabled).
// x_l stored fp16; fp32 accumulation. Final mean fused into layer-4 spmm.

#define NUM_NODES 200000
#define EMB_DIM   64
#define NUM_EDGES 6400000
#define VEC4      (EMB_DIM / 4)           // 16 float4 per node row (fp32)
#define NODE_F4   (NUM_NODES * VEC4)
#define ROW_U4    (EMB_DIM / 8)           // 8 uint4 per node row (fp16)
#define NODE_U4   (NUM_NODES * ROW_U4)

#define SCAN_B    1024
#define NPART     ((NUM_NODES + SCAN_B - 1) / SCAN_B)   // 196

// Scratch (allocation-free rule: static device arrays; zero-initialized at load).
__device__ uint4  g_embH[NODE_U4];        // fp16 embeds
__device__ uint4  g_x1[NODE_U4];          // fp16 layer outputs
__device__ uint4  g_x2[NODE_U4];
__device__ uint4  g_x3[NODE_U4];
__device__ int    g_cnt[NUM_NODES];       // zeroed at end of k_fill each call
__device__ int    g_rowptr[NUM_NODES + 1];
__device__ int    g_wpos[NUM_NODES];
__device__ int    g_part[256];
__device__ int2   g_edge[NUM_EDGES];      // {col, bitcast(val)} sorted by row

// ---------------------------------------------------------------------------
// Fused: row histogram (6.4M edges) + fp16 copy of embeds (3.2M float4).
// g_cnt is guaranteed zero on entry (zero-init on call 1; k_fill re-zeroes).
__global__ void k_init_hist(const int* __restrict__ rows,
                            const float4* __restrict__ emb)
{
    int i = blockIdx.x * blockDim.x + threadIdx.x;
    if (i < NUM_EDGES) atomicAdd(&g_cnt[rows[i]], 1);
    if (i < NODE_F4) {
        float4 v = emb[i];
        __half2 h0 = __floats2half2_rn(v.x, v.y);
        __half2 h1 = __floats2half2_rn(v.z, v.w);
        reinterpret_cast<uint2*>(g_embH)[i] =
            make_uint2(*(unsigned*)&h0, *(unsigned*)&h1);
    }
}

// Block-local exclusive scan of counts; per-block totals to g_part.
__global__ void k_scan_block()
{
    __shared__ int sh[SCAN_B];
    int t = threadIdx.x;
    int i = blockIdx.x * SCAN_B + t;
    int v = (i < NUM_NODES) ? g_cnt[i] : 0;
    sh[t] = v;
    __syncthreads();
    #pragma unroll
    for (int off = 1; off < SCAN_B; off <<= 1) {
        int tmp = 0;
        if (t >= off) tmp = sh[t - off];
        __syncthreads();
        if (t >= off) sh[t] += tmp;
        __syncthreads();
    }
    if (i < NUM_NODES) g_rowptr[i] = sh[t] - v;
    if (t == SCAN_B - 1) g_part[blockIdx.x] = sh[t];
}

// Merged: each block redundantly scans the <=256 partials in smem (cheap),
// then adds block offsets to rowptr, initializes write cursors, closes rowptr.
__global__ void k_scan_addpart()
{
    __shared__ int sh[256];
    int t = threadIdx.x;
    int v = (t < NPART) ? g_part[t] : 0;
    sh[t] = v;
    __syncthreads();
    #pragma unroll
    for (int off = 1; off < 256; off <<= 1) {
        int tmp = 0;
        if (t >= off) tmp = sh[t - off];
        __syncthreads();
        if (t >= off) sh[t] += tmp;
        __syncthreads();
    }
    // sh[p] now inclusive prefix; exclusive = sh[p] - part[p] handled below
    __syncthreads();

    int i = blockIdx.x * blockDim.x + t;
    if (i < NUM_NODES) {
        int p = i >> 10;
        int excl = sh[p] - g_part[p];   // exclusive prefix of partition p
        int r = g_rowptr[i] + excl;
        g_rowptr[i] = r;
        g_wpos[i] = r;
    }
    if (i == 0) g_rowptr[NUM_NODES] = NUM_EDGES;
}

// Scatter edges into row-sorted (col,val) pairs; re-zero g_cnt for next call.
__global__ void k_fill(const int* __restrict__ rows, const int* __restrict__ cols,
                       const float* __restrict__ vals)
{
    int e = blockIdx.x * blockDim.x + threadIdx.x;
    if (e < NUM_EDGES) {
        int r = rows[e];
        int p = atomicAdd(&g_wpos[r], 1);
        g_edge[p] = make_int2(cols[e], __float_as_int(vals[e]));
    }
    if (e < NUM_NODES) g_cnt[e] = 0;   // cnt dead after scan; prep next call
}

// ---------------------------------------------------------------------------
// 8 fp32 accumulators += v * fp16x8(u)
__device__ __forceinline__ void fma8(float acc[8], uint4 u, float v)
{
    float2 f0 = __half22float2(*reinterpret_cast<__half2*>(&u.x));
    float2 f1 = __half22float2(*reinterpret_cast<__half2*>(&u.y));
    float2 f2 = __half22float2(*reinterpret_cast<__half2*>(&u.z));
    float2 f3 = __half22float2(*reinterpret_cast<__half2*>(&u.w));
    acc[0] = fmaf(v, f0.x, acc[0]); acc[1] = fmaf(v, f0.y, acc[1]);
    acc[2] = fmaf(v, f1.x, acc[2]); acc[3] = fmaf(v, f1.y, acc[3]);
    acc[4] = fmaf(v, f2.x, acc[4]); acc[5] = fmaf(v, f2.y, acc[5]);
    acc[6] = fmaf(v, f3.x, acc[6]); acc[7] = fmaf(v, f3.y, acc[7]);
}

// Core CSR row-gather into fp32 acc.
__device__ __forceinline__ void row_gather(const uint4* __restrict__ x,
                                           int row, int q, float acc[8])
{
    int e   = __ldg(&g_rowptr[row]);
    int end = __ldg(&g_rowptr[row + 1]);

    for (; e + 3 < end; e += 4) {
        int2 cv0 = __ldg(&g_edge[e]);
        int2 cv1 = __ldg(&g_edge[e + 1]);
        int2 cv2 = __ldg(&g_edge[e + 2]);
        int2 cv3 = __ldg(&g_edge[e + 3]);
        uint4 x0 = __ldg(&x[cv0.x * ROW_U4 + q]);
        uint4 x1 = __ldg(&x[cv1.x * ROW_U4 + q]);
        uint4 x2 = __ldg(&x[cv2.x * ROW_U4 + q]);
        uint4 x3 = __ldg(&x[cv3.x * ROW_U4 + q]);
        fma8(acc, x0, __int_as_float(cv0.y));
        fma8(acc, x1, __int_as_float(cv1.y));
        fma8(acc, x2, __int_as_float(cv2.y));
        fma8(acc, x3, __int_as_float(cv3.y));
    }
    for (; e < end; e++) {
        int2 cv = __ldg(&g_edge[e]);
        uint4 xv = __ldg(&x[cv.x * ROW_U4 + q]);
        fma8(acc, xv, __int_as_float(cv.y));
    }
}

// CSR SpMM, gather-only, fp16 x -> fp16 dst. 8 threads/row, 8 dims each.
__global__ void k_spmm_csr(const uint4* __restrict__ x,
                           uint4* __restrict__ dst)
{
    int t = blockIdx.x * blockDim.x + threadIdx.x;
    int row = t >> 3;
    int q   = t & 7;
    if (row >= NUM_NODES) return;

    float acc[8] = {0.f, 0.f, 0.f, 0.f, 0.f, 0.f, 0.f, 0.f};
    row_gather(x, row, q, acc);

    __half2 h0 = __floats2half2_rn(acc[0], acc[1]);
    __half2 h1 = __floats2half2_rn(acc[2], acc[3]);
    __half2 h2 = __floats2half2_rn(acc[4], acc[5]);
    __half2 h3 = __floats2half2_rn(acc[6], acc[7]);
    dst[row * ROW_U4 + q] = make_uint4(*(unsigned*)&h0, *(unsigned*)&h1,
                                       *(unsigned*)&h2, *(unsigned*)&h3);
}

// Layer 4 fused with the mean: acc = x4 (fp32, never rounded);
// out = 0.2 * (embH + x1 + x2 + x3 + acc).  x = x3 input buffer.
__global__ void k_spmm_last(const uint4* __restrict__ x,
                            float4* __restrict__ out)
{
    int t = blockIdx.x * blockDim.x + threadIdx.x;
    int row = t >> 3;
    int q   = t & 7;
    if (row >= NUM_NODES) return;

    float acc[8] = {0.f, 0.f, 0.f, 0.f, 0.f, 0.f, 0.f, 0.f};
    row_gather(x, row, q, acc);

    // add own-row fp16 terms: embH, x1, x2, x3
    int o16 = row * ROW_U4 + q;
    uint4 u;
    #define ADD16(BUF) { \
        u = __ldg(&BUF[o16]); \
        float2 a0 = __half22float2(*reinterpret_cast<__half2*>(&u.x)); \
        float2 a1 = __half22float2(*reinterpret_cast<__half2*>(&u.y)); \
        float2 a2 = __half22float2(*reinterpret_cast<__half2*>(&u.z)); \
        float2 a3 = __half22float2(*reinterpret_cast<__half2*>(&u.w)); \
        acc[0] += a0.x; acc[1] += a0.y; acc[2] += a1.x; acc[3] += a1.y; \
        acc[4] += a2.x; acc[5] += a2.y; acc[6] += a3.x; acc[7] += a3.y; }
    ADD16(g_embH); ADD16(g_x1); ADD16(g_x2); ADD16(g_x3);
    #undef ADD16

    long long o = (long long)row * VEC4 + q * 2;
    out[o]     = make_float4(acc[0] * 0.2f, acc[1] * 0.2f,
                             acc[2] * 0.2f, acc[3] * 0.2f);
    out[o + 1] = make_float4(acc[4] * 0.2f, acc[5] * 0.2f,
                             acc[6] * 0.2f, acc[7] * 0.2f);
}

// ---------------------------------------------------------------------------
extern "C" void kernel_launch(void* const* d_in, const int* in_sizes, int n_in,
                              void* d_out, int out_size)
{
    const float4* emb  = (const float4*)d_in[0];
    const int*    rows = (const int*)d_in[1];
    const int*    cols = (const int*)d_in[2];
    const float*  vals = (const float*)d_in[3];
    float4*       out  = (float4*)d_out;

    uint4 *embH, *x1, *x2, *x3;
    cudaGetSymbolAddress((void**)&embH, g_embH);
    cudaGetSymbolAddress((void**)&x1, g_x1);
    cudaGetSymbolAddress((void**)&x2, g_x2);
    cudaGetSymbolAddress((void**)&x3, g_x3);

    const int TPB = 256;
    const int edge_blocks = (NUM_EDGES + TPB - 1) / TPB;
    const int node_blocks = (NUM_NODES + TPB - 1) / TPB;
    const long long spmm_threads = (long long)NUM_NODES * 8;
    const int spmm_blocks = (int)((spmm_threads + TPB - 1) / TPB);

    // CSR build (inside captured graph, every call)
    k_init_hist<<<edge_blocks, TPB>>>(rows, emb);
    k_scan_block<<<NPART, SCAN_B>>>();
    k_scan_addpart<<<node_blocks, TPB>>>();
    k_fill<<<edge_blocks, TPB>>>(rows, cols, vals);

    // 4 propagation layers; layer 4 fused with the mean-combine.
    k_spmm_csr<<<spmm_blocks, TPB>>>(embH, x1);
    k_spmm_csr<<<spmm_blocks, TPB>>>(x1, x2);
    k_spmm_csr<<<spmm_blocks, TPB>>>(x2, x3);
    k_spmm_last<<<spmm_blocks, TPB>>>(x3, out);
}